// round 7
// baseline (speedup 1.0000x reference)
#include <cuda_runtime.h>
#include <math.h>
#include <stdint.h>

// ---------------- problem constants ----------------
#define BATCH 4
#define SEQ   2048
#define DIM   768
#define HEADS 12
#define DHEAD 64
#define DFF   3072
#define ROWS  (BATCH*SEQ)          // 8192
#define QKVC  (3*DIM)              // 2304
#define EPSLN 1e-5f
#define NW    (DIM*DIM)            // 589824

// ---------------- scratch (device globals; no allocation) ----------------
__device__ float g_ln1 [ROWS*DIM];
__device__ float g_qkv [ROWS*QKVC];
__device__ float g_y   [ROWS*DIM];
__device__ float g_x2  [ROWS*DIM];
__device__ float g_ln2 [ROWS*DIM];
__device__ float g_h   [ROWS*DFF];
__device__ float g_wqkv[QKVC*DIM];   // packed tf32 [2304][768]
__device__ float g_woT [DIM*DIM];    // w_o transposed, tf32 [768][768]
__device__ float g_w1  [DFF*DIM];    // tf32
__device__ float g_w2  [DIM*DFF];    // tf32

// ---------------- helpers ----------------
__device__ __forceinline__ float to_tf32(float x) {
    uint32_t u;
    asm("cvt.rna.tf32.f32 %0, %1;" : "=r"(u) : "f"(x));
    return __uint_as_float(u);
}

__device__ __forceinline__ void mma_tf32(float* d, const uint32_t* a, const uint32_t* b) {
    asm volatile(
        "mma.sync.aligned.m16n8k8.row.col.f32.tf32.tf32.f32 "
        "{%0,%1,%2,%3}, {%4,%5,%6,%7}, {%8,%9}, {%0,%1,%2,%3};"
        : "+f"(d[0]), "+f"(d[1]), "+f"(d[2]), "+f"(d[3])
        : "r"(a[0]), "r"(a[1]), "r"(a[2]), "r"(a[3]), "r"(b[0]), "r"(b[1]));
}

__device__ __forceinline__ void cp_async16(void* smem_dst, const void* gmem_src) {
    unsigned d = (unsigned)__cvta_generic_to_shared(smem_dst);
    asm volatile("cp.async.cg.shared.global [%0], [%1], 16;" :: "r"(d), "l"(gmem_src));
}
__device__ __forceinline__ void cp_commit() { asm volatile("cp.async.commit_group;"); }
__device__ __forceinline__ void cp_wait0()  { asm volatile("cp.async.wait_group 0;"); }

// ---------------- prep 1: pack+convert QKV weights ----------------
__global__ void prep_qkv_kernel(const float* __restrict__ wq, const float* __restrict__ wk,
                                const float* __restrict__ wv, float* __restrict__ out) {
    int i = blockIdx.x * blockDim.x + threadIdx.x;
    if (i < NW)               out[i] = to_tf32(wq[i]);
    else if (i < 2 * NW)      out[i] = to_tf32(wk[i - NW]);
    else if (i < 3 * NW)      out[i] = to_tf32(wv[i - 2 * NW]);
}

// ---------------- prep 2: W1, W2 convert + w_o transpose-convert ----------------
__global__ void prep_mlp_kernel(const float* __restrict__ W1, const float* __restrict__ W2,
                                const float* __restrict__ wo,
                                float* __restrict__ o1, float* __restrict__ o2,
                                float* __restrict__ oT) {
    int i = blockIdx.x * blockDim.x + threadIdx.x;
    const int N1 = DFF * DIM;
    if (i < N1) { o1[i] = to_tf32(W1[i]); return; }
    i -= N1;
    if (i < N1) { o2[i] = to_tf32(W2[i]); return; }
    i -= N1;
    if (i < NW) {
        const int n = i / DIM, k = i - n * DIM;   // oT[n][k] = wo[k][n]
        oT[i] = to_tf32(wo[(size_t)k * DIM + n]);
    }
}

// ---------------- LayerNorm: one block per row (tf32-rounded output) ----------------
__global__ __launch_bounds__(256)
void ln_kernel(const float* __restrict__ X, const float* __restrict__ gam,
               const float* __restrict__ bet, float* __restrict__ out) {
    const int row = blockIdx.x;
    const int tid = threadIdx.x;
    const float* x = X + (size_t)row * DIM;

    float v0 = x[tid], v1 = x[tid + 256], v2 = x[tid + 512];

    __shared__ float sh[8];
    float s = v0 + v1 + v2;
    #pragma unroll
    for (int o = 16; o; o >>= 1) s += __shfl_xor_sync(0xffffffffu, s, o);
    if ((tid & 31) == 0) sh[tid >> 5] = s;
    __syncthreads();
    float mu = 0.f;
    #pragma unroll
    for (int j = 0; j < 8; j++) mu += sh[j];
    mu *= (1.f / DIM);
    __syncthreads();

    float d0 = v0 - mu, d1 = v1 - mu, d2 = v2 - mu;
    float q = d0*d0 + d1*d1 + d2*d2;
    #pragma unroll
    for (int o = 16; o; o >>= 1) q += __shfl_xor_sync(0xffffffffu, q, o);
    if ((tid & 31) == 0) sh[tid >> 5] = q;
    __syncthreads();
    float var = 0.f;
    #pragma unroll
    for (int j = 0; j < 8; j++) var += sh[j];
    const float rstd = rsqrtf(var * (1.f / DIM) + EPSLN);

    float* o = out + (size_t)row * DIM;
    o[tid      ] = to_tf32(d0 * rstd * gam[tid      ] + bet[tid      ]);
    o[tid + 256] = to_tf32(d1 * rstd * gam[tid + 256] + bet[tid + 256]);
    o[tid + 512] = to_tf32(d2 * rstd * gam[tid + 512] + bet[tid + 512]);
}

// ---------------- tf32 tensor-core GEMM ----------------
// C[M,N] = A[M,K] @ B[N,K]^T  (+bias)(relu)(+res)(tf32-round output)
// BM=BN=128, BK=16, 128 threads = 4 warps (2M x 2N), warp tile 64x64.
// Double-buffered cp.async. Conflict-free stride-20 smem.
template<bool BIAS, bool RELU, bool RES, bool CVT>
__global__ __launch_bounds__(128, 2)
void gemm_tc(const float* __restrict__ A, const float* __restrict__ B,
             const float* __restrict__ bias, const float* __restrict__ res,
             float* __restrict__ C, int M, int N, int K) {
    __shared__ float As[2][128][20];
    __shared__ float Bs[2][128][20];

    const int tid  = threadIdx.x;
    const int warp = tid >> 5, lane = tid & 31;
    const int wm   = (warp & 1) * 64;
    const int wn   = (warp >> 1) * 64;
    const int m0   = blockIdx.y * 128;
    const int n0   = blockIdx.x * 128;
    const int r    = lane >> 2;
    const int c    = lane & 3;

    float acc[4][8][4];
    #pragma unroll
    for (int i = 0; i < 4; i++)
        #pragma unroll
        for (int j = 0; j < 8; j++)
            #pragma unroll
            for (int q = 0; q < 4; q++) acc[i][j][q] = 0.f;

    const int KT = K >> 4;

    {
        #pragma unroll
        for (int i = 0; i < 4; i++) {
            const int idx = tid + i * 128;
            const int row = idx >> 2, k4 = (idx & 3) << 2;
            cp_async16(&As[0][row][k4], A + (size_t)(m0 + row) * K + k4);
            cp_async16(&Bs[0][row][k4], B + (size_t)(n0 + row) * K + k4);
        }
        cp_commit();
    }

    for (int kt = 0; kt < KT; kt++) {
        const int st = kt & 1;
        cp_wait0();
        __syncthreads();

        if (kt + 1 < KT) {
            const int k0 = (kt + 1) << 4;
            const int sn = st ^ 1;
            #pragma unroll
            for (int i = 0; i < 4; i++) {
                const int idx = tid + i * 128;
                const int row = idx >> 2, k4 = (idx & 3) << 2;
                cp_async16(&As[sn][row][k4], A + (size_t)(m0 + row) * K + k0 + k4);
                cp_async16(&Bs[sn][row][k4], B + (size_t)(n0 + row) * K + k0 + k4);
            }
            cp_commit();
        }

        #pragma unroll
        for (int kh = 0; kh < 2; kh++) {
            const int ks = kh * 8;
            uint32_t af[4][4], bf[8][2];
            #pragma unroll
            for (int i = 0; i < 4; i++) {
                const int mb = wm + i * 16;
                af[i][0] = __float_as_uint(As[st][mb + r    ][ks + c    ]);
                af[i][1] = __float_as_uint(As[st][mb + r + 8][ks + c    ]);
                af[i][2] = __float_as_uint(As[st][mb + r    ][ks + c + 4]);
                af[i][3] = __float_as_uint(As[st][mb + r + 8][ks + c + 4]);
            }
            #pragma unroll
            for (int j = 0; j < 8; j++) {
                const int nb = wn + j * 8;
                bf[j][0] = __float_as_uint(Bs[st][nb + r][ks + c    ]);
                bf[j][1] = __float_as_uint(Bs[st][nb + r][ks + c + 4]);
            }
            #pragma unroll
            for (int i = 0; i < 4; i++)
                #pragma unroll
                for (int j = 0; j < 8; j++)
                    mma_tf32(acc[i][j], af[i], bf[j]);
        }
        __syncthreads();
    }

    #pragma unroll
    for (int i = 0; i < 4; i++) {
        const int m = m0 + wm + i * 16 + r;
        #pragma unroll
        for (int j = 0; j < 8; j++) {
            const int n = n0 + wn + j * 8 + 2 * c;
            float v0 = acc[i][j][0], v1 = acc[i][j][1];
            float v2 = acc[i][j][2], v3 = acc[i][j][3];
            if (BIAS) {
                const float b0 = bias[n], b1 = bias[n + 1];
                v0 += b0; v1 += b1; v2 += b0; v3 += b1;
            }
            if (RELU) {
                v0 = fmaxf(v0, 0.f); v1 = fmaxf(v1, 0.f);
                v2 = fmaxf(v2, 0.f); v3 = fmaxf(v3, 0.f);
            }
            if (RES) {
                v0 += res[(size_t)m * N + n];
                v1 += res[(size_t)m * N + n + 1];
                v2 += res[(size_t)(m + 8) * N + n];
                v3 += res[(size_t)(m + 8) * N + n + 1];
            }
            if (CVT) {
                v0 = to_tf32(v0); v1 = to_tf32(v1);
                v2 = to_tf32(v2); v3 = to_tf32(v3);
            }
            *reinterpret_cast<float2*>(&C[(size_t)m * N + n])       = make_float2(v0, v1);
            *reinterpret_cast<float2*>(&C[(size_t)(m + 8) * N + n]) = make_float2(v2, v3);
        }
    }
}

// ---------------- tensor-core causal flash attention ----------------
// qkv: [row][2304], q|k|v at col offsets 0|768|1536 (+h*64). All tf32-rounded.
__global__ __launch_bounds__(128, 4)
void flash_attn(const float* __restrict__ qkv, float* __restrict__ Y) {
    __shared__ float Ks[64][68];   // K tile; reused to hold P after QK
    __shared__ float Vs[64][72];   // V tile [s][d]

    const int warp = threadIdx.x >> 5;
    const int lane = threadIdx.x & 31;
    const int r    = lane >> 2;
    const int c    = lane & 3;
    const int qt   = (int)gridDim.x - 1 - (int)blockIdx.x;  // longest first
    const int h    = blockIdx.y;
    const int b    = blockIdx.z;
    const int t0   = qt * 64;
    const int wm   = warp * 16;

    uint32_t aq[8][4];
    {
        const float* q0 = qkv + (size_t)(b * SEQ + t0 + wm + r) * QKVC + h * 64;
        const float* q1 = q0 + 8 * (size_t)QKVC;
        #pragma unroll
        for (int ks = 0; ks < 8; ks++) {
            aq[ks][0] = __float_as_uint(q0[ks * 8 + c    ] * 0.125f);
            aq[ks][1] = __float_as_uint(q1[ks * 8 + c    ] * 0.125f);
            aq[ks][2] = __float_as_uint(q0[ks * 8 + c + 4] * 0.125f);
            aq[ks][3] = __float_as_uint(q1[ks * 8 + c + 4] * 0.125f);
        }
    }

    float acc_o[8][4];
    #pragma unroll
    for (int j = 0; j < 8; j++)
        #pragma unroll
        for (int q = 0; q < 4; q++) acc_o[j][q] = 0.f;
    float m0s = -1e30f, m1s = -1e30f, l0s = 0.f, l1s = 0.f;

    for (int s0 = 0; s0 <= t0; s0 += 64) {
        __syncthreads();

        #pragma unroll
        for (int it = 0; it < 8; it++) {
            const int idx = threadIdx.x + it * 128;
            const int row = idx >> 4;
            const int c4  = (idx & 15) << 2;
            const float* src = qkv + (size_t)(b * SEQ + s0 + row) * QKVC + h * 64 + c4;
            *reinterpret_cast<float4*>(&Ks[row][c4]) =
                *reinterpret_cast<const float4*>(src + 768);
            *reinterpret_cast<float4*>(&Vs[row][c4]) =
                *reinterpret_cast<const float4*>(src + 1536);
        }
        __syncthreads();

        float acc_s[8][4];
        #pragma unroll
        for (int j = 0; j < 8; j++)
            #pragma unroll
            for (int q = 0; q < 4; q++) acc_s[j][q] = 0.f;

        #pragma unroll
        for (int ks = 0; ks < 8; ks++) {
            #pragma unroll
            for (int j = 0; j < 8; j++) {
                uint32_t bf[2];
                bf[0] = __float_as_uint(Ks[8 * j + r][8 * ks + c    ]);
                bf[1] = __float_as_uint(Ks[8 * j + r][8 * ks + c + 4]);
                mma_tf32(acc_s[j], aq[ks], bf);
            }
        }

        if (s0 == t0) {
            #pragma unroll
            for (int j = 0; j < 8; j++) {
                const int n = 8 * j + 2 * c;
                const int mr0 = wm + r, mr1 = wm + r + 8;
                if (n     > mr0) acc_s[j][0] = -1e30f;
                if (n + 1 > mr0) acc_s[j][1] = -1e30f;
                if (n     > mr1) acc_s[j][2] = -1e30f;
                if (n + 1 > mr1) acc_s[j][3] = -1e30f;
            }
        }

        float tm0 = -1e30f, tm1 = -1e30f;
        #pragma unroll
        for (int j = 0; j < 8; j++) {
            tm0 = fmaxf(tm0, fmaxf(acc_s[j][0], acc_s[j][1]));
            tm1 = fmaxf(tm1, fmaxf(acc_s[j][2], acc_s[j][3]));
        }
        #pragma unroll
        for (int o = 1; o < 4; o <<= 1) {
            tm0 = fmaxf(tm0, __shfl_xor_sync(0xffffffffu, tm0, o));
            tm1 = fmaxf(tm1, __shfl_xor_sync(0xffffffffu, tm1, o));
        }
        const float mn0 = fmaxf(m0s, tm0);
        const float mn1 = fmaxf(m1s, tm1);
        const float cr0 = __expf(m0s - mn0);
        const float cr1 = __expf(m1s - mn1);

        __syncthreads();

        float sum0 = 0.f, sum1 = 0.f;
        #pragma unroll
        for (int j = 0; j < 8; j++) {
            const float p0 = __expf(acc_s[j][0] - mn0);
            const float p1 = __expf(acc_s[j][1] - mn0);
            const float p2 = __expf(acc_s[j][2] - mn1);
            const float p3 = __expf(acc_s[j][3] - mn1);
            sum0 += p0 + p1;
            sum1 += p2 + p3;
            *reinterpret_cast<float2*>(&Ks[wm + r    ][8 * j + 2 * c]) =
                make_float2(to_tf32(p0), to_tf32(p1));
            *reinterpret_cast<float2*>(&Ks[wm + r + 8][8 * j + 2 * c]) =
                make_float2(to_tf32(p2), to_tf32(p3));
        }
        #pragma unroll
        for (int o = 1; o < 4; o <<= 1) {
            sum0 += __shfl_xor_sync(0xffffffffu, sum0, o);
            sum1 += __shfl_xor_sync(0xffffffffu, sum1, o);
        }
        l0s = l0s * cr0 + sum0;
        l1s = l1s * cr1 + sum1;
        m0s = mn0;
        m1s = mn1;
        #pragma unroll
        for (int j = 0; j < 8; j++) {
            acc_o[j][0] *= cr0; acc_o[j][1] *= cr0;
            acc_o[j][2] *= cr1; acc_o[j][3] *= cr1;
        }
        __syncwarp();

        #pragma unroll
        for (int ks = 0; ks < 8; ks++) {
            uint32_t ap[4];
            ap[0] = __float_as_uint(Ks[wm + r    ][8 * ks + c    ]);
            ap[1] = __float_as_uint(Ks[wm + r + 8][8 * ks + c    ]);
            ap[2] = __float_as_uint(Ks[wm + r    ][8 * ks + c + 4]);
            ap[3] = __float_as_uint(Ks[wm + r + 8][8 * ks + c + 4]);
            #pragma unroll
            for (int j = 0; j < 8; j++) {
                uint32_t bf[2];
                bf[0] = __float_as_uint(Vs[8 * ks + c    ][8 * j + r]);
                bf[1] = __float_as_uint(Vs[8 * ks + c + 4][8 * j + r]);
                mma_tf32(acc_o[j], ap, bf);
            }
        }
    }

    const float inv0 = 1.f / l0s;
    const float inv1 = 1.f / l1s;
    float* y0 = Y + (size_t)(b * SEQ + t0 + wm + r) * DIM + h * 64;
    float* y1 = y0 + 8 * (size_t)DIM;
    #pragma unroll
    for (int j = 0; j < 8; j++) {
        const int n = 8 * j + 2 * c;
        *reinterpret_cast<float2*>(y0 + n) =
            make_float2(to_tf32(acc_o[j][0] * inv0), to_tf32(acc_o[j][1] * inv0));
        *reinterpret_cast<float2*>(y1 + n) =
            make_float2(to_tf32(acc_o[j][2] * inv1), to_tf32(acc_o[j][3] * inv1));
    }
}

// ---------------- launch ----------------
extern "C" void kernel_launch(void* const* d_in, const int* in_sizes, int n_in,
                              void* d_out, int out_size) {
    const float* X   = (const float*)d_in[0];
    const float* w_q = (const float*)d_in[1];
    const float* w_k = (const float*)d_in[2];
    const float* w_v = (const float*)d_in[3];
    const float* w_o = (const float*)d_in[4];
    const float* W1  = (const float*)d_in[5];
    const float* b1  = (const float*)d_in[6];
    const float* W2  = (const float*)d_in[7];
    const float* b2  = (const float*)d_in[8];
    const float* g1  = (const float*)d_in[9];
    const float* be1 = (const float*)d_in[10];
    const float* g2  = (const float*)d_in[11];
    const float* be2 = (const float*)d_in[12];
    float* out = (float*)d_out;

    float *p_ln1, *p_qkv, *p_y, *p_x2, *p_ln2, *p_h;
    float *p_wqkv, *p_woT, *p_w1, *p_w2;
    cudaGetSymbolAddress((void**)&p_ln1,  g_ln1);
    cudaGetSymbolAddress((void**)&p_qkv,  g_qkv);
    cudaGetSymbolAddress((void**)&p_y,    g_y);
    cudaGetSymbolAddress((void**)&p_x2,   g_x2);
    cudaGetSymbolAddress((void**)&p_ln2,  g_ln2);
    cudaGetSymbolAddress((void**)&p_h,    g_h);
    cudaGetSymbolAddress((void**)&p_wqkv, g_wqkv);
    cudaGetSymbolAddress((void**)&p_woT,  g_woT);
    cudaGetSymbolAddress((void**)&p_w1,   g_w1);
    cudaGetSymbolAddress((void**)&p_w2,   g_w2);

    // launch 0: prep QKV weights
    prep_qkv_kernel<<<(3 * NW + 255) / 256, 256>>>(w_q, w_k, w_v, p_wqkv);
    // launch 1: prep MLP weights + w_o transpose
    {
        const int tot = 2 * DFF * DIM + NW;
        prep_mlp_kernel<<<(tot + 255) / 256, 256>>>(W1, W2, w_o, p_w1, p_w2, p_woT);
    }
    // launch 2: LN1
    ln_kernel<<<ROWS, 256>>>(X, g1, be1, p_ln1);
    // launch 3: fused QKV projection (tf32 out)
    {
        dim3 grid(QKVC / 128, ROWS / 128);
        gemm_tc<false,false,false,true><<<grid, 128>>>(p_ln1, p_wqkv, nullptr, nullptr, p_qkv, ROWS, QKVC, DIM);
    }
    // launch 4: flash attention
    {
        dim3 grid(SEQ / 64, HEADS, BATCH);
        flash_attn<<<grid, 128>>>(p_qkv, p_y);
    }
    // launch 5 (ncu -s 5 captures this): O-projection + residual
    {
        dim3 grid(DIM / 128, ROWS / 128);
        gemm_tc<false,false,true,false><<<grid, 128>>>(p_y, p_woT, nullptr, X, p_x2, ROWS, DIM, DIM);
    }
    // launch 6: LN2
    ln_kernel<<<ROWS, 256>>>(p_x2, g2, be2, p_ln2);
    // launch 7: MLP up
    {
        dim3 grid(DFF / 128, ROWS / 128);
        gemm_tc<true,true,false,true><<<grid, 128>>>(p_ln2, p_w1, b1, nullptr, p_h, ROWS, DFF, DIM);
    }
    // launch 8: MLP down + residual -> out
    {
        dim3 grid(DIM / 128, ROWS / 128);
        gemm_tc<true,false,true,false><<<grid, 128>>>(p_h, p_w2, b2, p_x2, out, ROWS, DIM, DFF);
    }
}

// round 8
// speedup vs baseline: 1.0265x; 1.0265x over previous
#include <cuda_runtime.h>
#include <math.h>
#include <stdint.h>

// ---------------- problem constants ----------------
#define BATCH 4
#define SEQ   2048
#define DIM   768
#define HEADS 12
#define DHEAD 64
#define DFF   3072
#define ROWS  (BATCH*SEQ)          // 8192
#define QKVC  (3*DIM)              // 2304
#define EPSLN 1e-5f
#define NW    (DIM*DIM)            // 589824

// column permutation within 16-groups: bits b3b2b1b0 -> b1b0b3b2 (involution)
#define PERMC(n) (((n) & ~15) | (((n) & 3) << 2) | (((n) >> 2) & 3))

// ---------------- scratch (device globals; no allocation) ----------------
__device__ float g_ln1 [ROWS*DIM];   // k-permuted
__device__ float g_qkv [ROWS*QKVC];  // natural (attention reads it)
__device__ float g_y   [ROWS*DIM];   // k-permuted
__device__ float g_x2  [ROWS*DIM];   // natural (ln2 reads it)
__device__ float g_ln2 [ROWS*DIM];   // k-permuted
__device__ float g_h   [ROWS*DFF];   // k-permuted
__device__ float g_wqkv[QKVC*DIM];   // packed tf32, k-permuted
__device__ float g_woT [DIM*DIM];    // w_o^T, tf32, k-permuted
__device__ float g_w1  [DFF*DIM];    // tf32, k-permuted
__device__ float g_w2  [DIM*DFF];    // tf32, k-permuted

// ---------------- helpers ----------------
__device__ __forceinline__ float to_tf32(float x) {
    uint32_t u;
    asm("cvt.rna.tf32.f32 %0, %1;" : "=r"(u) : "f"(x));
    return __uint_as_float(u);
}

__device__ __forceinline__ void mma_tf32(float* d, const uint32_t* a, const uint32_t* b) {
    asm volatile(
        "mma.sync.aligned.m16n8k8.row.col.f32.tf32.tf32.f32 "
        "{%0,%1,%2,%3}, {%4,%5,%6,%7}, {%8,%9}, {%0,%1,%2,%3};"
        : "+f"(d[0]), "+f"(d[1]), "+f"(d[2]), "+f"(d[3])
        : "r"(a[0]), "r"(a[1]), "r"(a[2]), "r"(a[3]), "r"(b[0]), "r"(b[1]));
}

__device__ __forceinline__ void cp_async16(void* smem_dst, const void* gmem_src) {
    unsigned d = (unsigned)__cvta_generic_to_shared(smem_dst);
    asm volatile("cp.async.cg.shared.global [%0], [%1], 16;" :: "r"(d), "l"(gmem_src));
}
__device__ __forceinline__ void cp_commit() { asm volatile("cp.async.commit_group;"); }
__device__ __forceinline__ void cp_wait0()  { asm volatile("cp.async.wait_group 0;"); }
__device__ __forceinline__ void cp_wait1()  { asm volatile("cp.async.wait_group 1;"); }

// ---------------- prep 1: pack+convert QKV weights (k-permuted) ----------------
__global__ void prep_qkv_kernel(const float* __restrict__ wq, const float* __restrict__ wk,
                                const float* __restrict__ wv, float* __restrict__ out) {
    int i = blockIdx.x * blockDim.x + threadIdx.x;
    if (i >= 3 * NW) return;
    const float* src = (i < NW) ? wq : (i < 2 * NW ? wk : wv);
    int j = (i < NW) ? i : (i < 2 * NW ? i - NW : i - 2 * NW);
    const int n = j / DIM, kk = j - n * DIM;
    out[i] = to_tf32(src[(size_t)n * DIM + PERMC(kk)]);
}

// ---------------- prep 2: W1, W2 convert + w_o transpose (all k-permuted) ----------------
__global__ void prep_mlp_kernel(const float* __restrict__ W1, const float* __restrict__ W2,
                                const float* __restrict__ wo,
                                float* __restrict__ o1, float* __restrict__ o2,
                                float* __restrict__ oT) {
    int i = blockIdx.x * blockDim.x + threadIdx.x;
    const int N1 = DFF * DIM;
    if (i < N1) {  // W1 [DFF][DIM], k=DIM
        const int n = i / DIM, kk = i - n * DIM;
        o1[i] = to_tf32(W1[(size_t)n * DIM + PERMC(kk)]);
        return;
    }
    i -= N1;
    if (i < N1) {  // W2 [DIM][DFF], k=DFF
        const int n = i / DFF, kk = i - n * DFF;
        o2[i] = to_tf32(W2[(size_t)n * DFF + PERMC(kk)]);
        return;
    }
    i -= N1;
    if (i < NW) {  // oT[n][k] = wo[k][n], k permuted
        const int n = i / DIM, kk = i - n * DIM;
        oT[i] = to_tf32(wo[(size_t)PERMC(kk) * DIM + n]);
    }
}

// ---------------- LayerNorm: one block per row (tf32, k-permuted output) ----------------
__global__ __launch_bounds__(256)
void ln_kernel(const float* __restrict__ X, const float* __restrict__ gam,
               const float* __restrict__ bet, float* __restrict__ out) {
    const int row = blockIdx.x;
    const int tid = threadIdx.x;
    const float* x = X + (size_t)row * DIM;

    float v0 = x[tid], v1 = x[tid + 256], v2 = x[tid + 512];

    __shared__ float sh[8];
    float s = v0 + v1 + v2;
    #pragma unroll
    for (int o = 16; o; o >>= 1) s += __shfl_xor_sync(0xffffffffu, s, o);
    if ((tid & 31) == 0) sh[tid >> 5] = s;
    __syncthreads();
    float mu = 0.f;
    #pragma unroll
    for (int j = 0; j < 8; j++) mu += sh[j];
    mu *= (1.f / DIM);
    __syncthreads();

    float d0 = v0 - mu, d1 = v1 - mu, d2 = v2 - mu;
    float q = d0*d0 + d1*d1 + d2*d2;
    #pragma unroll
    for (int o = 16; o; o >>= 1) q += __shfl_xor_sync(0xffffffffu, q, o);
    if ((tid & 31) == 0) sh[tid >> 5] = q;
    __syncthreads();
    float var = 0.f;
    #pragma unroll
    for (int j = 0; j < 8; j++) var += sh[j];
    const float rstd = rsqrtf(var * (1.f / DIM) + EPSLN);

    float* o = out + (size_t)row * DIM;
    const int pt = PERMC(tid);   // logical col tid stored at physical PERMC(tid)
    o[pt      ] = to_tf32(d0 * rstd * gam[tid      ] + bet[tid      ]);
    o[pt + 256] = to_tf32(d1 * rstd * gam[tid + 256] + bet[tid + 256]);
    o[pt + 512] = to_tf32(d2 * rstd * gam[tid + 512] + bet[tid + 512]);
}

// ---------------- tf32 tensor-core GEMM (k-permuted operands) ----------------
// C[M,N] = A[M,K] @ B[N,K]^T. A,B physically k-permuted (slot s holds logical
// PERMC(s)); fragment quads come from single LDS.128 per row. XOR chunk swizzle
// -> conflict-free. 3-stage cp.async ring. BM=BN=128, BK=16, 4 warps (64x64).
template<bool BIAS, bool RELU, bool RES, bool CVT, bool PERM>
__global__ __launch_bounds__(128, 2)
void gemm_tc(const float* __restrict__ A, const float* __restrict__ B,
             const float* __restrict__ bias, const float* __restrict__ res,
             float* __restrict__ C, int M, int N, int K) {
    __shared__ float As[3][128][16];
    __shared__ float Bs[3][128][16];

    const int tid  = threadIdx.x;
    const int warp = tid >> 5, lane = tid & 31;
    const int wm   = (warp & 1) * 64;
    const int wn   = (warp >> 1) * 64;
    const int m0   = blockIdx.y * 128;
    const int n0   = blockIdx.x * 128;
    const int r    = lane >> 2;
    const int c    = lane & 3;
    const int rc   = (c ^ (r & 3)) * 4;   // read chunk offset (floats)

    float acc[4][8][4];
    #pragma unroll
    for (int i = 0; i < 4; i++)
        #pragma unroll
        for (int j = 0; j < 8; j++)
            #pragma unroll
            for (int q = 0; q < 4; q++) acc[i][j][q] = 0.f;

    const int KT = K >> 4;

    auto load_stage = [&](int s, int k0) {
        #pragma unroll
        for (int i = 0; i < 4; i++) {
            const int idx = tid + i * 128;
            const int row = idx >> 2, ch = idx & 3;
            const int wch = (ch ^ (row & 3)) << 2;
            cp_async16(&As[s][row][wch], A + (size_t)(m0 + row) * K + k0 + ch * 4);
            cp_async16(&Bs[s][row][wch], B + (size_t)(n0 + row) * K + k0 + ch * 4);
        }
        cp_commit();
    };

    load_stage(0, 0);
    load_stage(1, 16);

    for (int kt = 0; kt < KT; kt++) {
        const int st = kt % 3;
        if (kt + 2 < KT) cp_wait1(); else cp_wait0();
        __syncthreads();
        if (kt + 2 < KT) load_stage((kt + 2) % 3, (kt + 2) << 4);

        // one LDS.128 per row -> fragment quads for both kh halves
        float4 a4lo[4], a4hi[4], b4[8];
        #pragma unroll
        for (int i = 0; i < 4; i++) {
            const int row = wm + i * 16 + r;
            a4lo[i] = *reinterpret_cast<const float4*>(&As[st][row    ][rc]);
            a4hi[i] = *reinterpret_cast<const float4*>(&As[st][row + 8][rc]);
        }
        #pragma unroll
        for (int j = 0; j < 8; j++)
            b4[j] = *reinterpret_cast<const float4*>(&Bs[st][wn + j * 8 + r][rc]);

        #pragma unroll
        for (int i = 0; i < 4; i++) {
            uint32_t af[4];
            af[0] = __float_as_uint(a4lo[i].x); af[1] = __float_as_uint(a4hi[i].x);
            af[2] = __float_as_uint(a4lo[i].y); af[3] = __float_as_uint(a4hi[i].y);
            #pragma unroll
            for (int j = 0; j < 8; j++) {
                uint32_t bf[2] = { __float_as_uint(b4[j].x), __float_as_uint(b4[j].y) };
                mma_tf32(acc[i][j], af, bf);
            }
        }
        #pragma unroll
        for (int i = 0; i < 4; i++) {
            uint32_t af[4];
            af[0] = __float_as_uint(a4lo[i].z); af[1] = __float_as_uint(a4hi[i].z);
            af[2] = __float_as_uint(a4lo[i].w); af[3] = __float_as_uint(a4hi[i].w);
            #pragma unroll
            for (int j = 0; j < 8; j++) {
                uint32_t bf[2] = { __float_as_uint(b4[j].z), __float_as_uint(b4[j].w) };
                mma_tf32(acc[i][j], af, bf);
            }
        }
    }

    #pragma unroll
    for (int i = 0; i < 4; i++) {
        const int m = m0 + wm + i * 16 + r;
        #pragma unroll
        for (int j = 0; j < 8; j++) {
            const int n = n0 + wn + j * 8 + 2 * c;
            float v0 = acc[i][j][0], v1 = acc[i][j][1];
            float v2 = acc[i][j][2], v3 = acc[i][j][3];
            if (BIAS) {
                const float b0 = bias[n], b1 = bias[n + 1];
                v0 += b0; v1 += b1; v2 += b0; v3 += b1;
            }
            if (RELU) {
                v0 = fmaxf(v0, 0.f); v1 = fmaxf(v1, 0.f);
                v2 = fmaxf(v2, 0.f); v3 = fmaxf(v3, 0.f);
            }
            if (RES) {
                v0 += res[(size_t)m * N + n];
                v1 += res[(size_t)m * N + n + 1];
                v2 += res[(size_t)(m + 8) * N + n];
                v3 += res[(size_t)(m + 8) * N + n + 1];
            }
            if (CVT) {
                v0 = to_tf32(v0); v1 = to_tf32(v1);
                v2 = to_tf32(v2); v3 = to_tf32(v3);
            }
            if (PERM) {
                const int p = PERMC(n);   // n even => n+1 maps to p+4
                C[(size_t)m * N + p]           = v0;
                C[(size_t)m * N + p + 4]       = v1;
                C[(size_t)(m + 8) * N + p]     = v2;
                C[(size_t)(m + 8) * N + p + 4] = v3;
            } else {
                *reinterpret_cast<float2*>(&C[(size_t)m * N + n])       = make_float2(v0, v1);
                *reinterpret_cast<float2*>(&C[(size_t)(m + 8) * N + n]) = make_float2(v2, v3);
            }
        }
    }
}

// ---------------- tensor-core causal flash attention ----------------
// qkv natural layout; Y written tf32 + k-permuted (feeds O-proj GEMM).
__global__ __launch_bounds__(128, 4)
void flash_attn(const float* __restrict__ qkv, float* __restrict__ Y) {
    __shared__ float Ks[64][68];   // K tile; reused to hold P after QK
    __shared__ float Vs[64][72];   // V tile [s][d]

    const int warp = threadIdx.x >> 5;
    const int lane = threadIdx.x & 31;
    const int r    = lane >> 2;
    const int c    = lane & 3;
    const int qt   = (int)gridDim.x - 1 - (int)blockIdx.x;  // longest first
    const int h    = blockIdx.y;
    const int b    = blockIdx.z;
    const int t0   = qt * 64;
    const int wm   = warp * 16;

    uint32_t aq[8][4];
    {
        const float* q0 = qkv + (size_t)(b * SEQ + t0 + wm + r) * QKVC + h * 64;
        const float* q1 = q0 + 8 * (size_t)QKVC;
        #pragma unroll
        for (int ks = 0; ks < 8; ks++) {
            aq[ks][0] = __float_as_uint(q0[ks * 8 + c    ] * 0.125f);
            aq[ks][1] = __float_as_uint(q1[ks * 8 + c    ] * 0.125f);
            aq[ks][2] = __float_as_uint(q0[ks * 8 + c + 4] * 0.125f);
            aq[ks][3] = __float_as_uint(q1[ks * 8 + c + 4] * 0.125f);
        }
    }

    float acc_o[8][4];
    #pragma unroll
    for (int j = 0; j < 8; j++)
        #pragma unroll
        for (int q = 0; q < 4; q++) acc_o[j][q] = 0.f;
    float m0s = -1e30f, m1s = -1e30f, l0s = 0.f, l1s = 0.f;

    for (int s0 = 0; s0 <= t0; s0 += 64) {
        __syncthreads();

        #pragma unroll
        for (int it = 0; it < 8; it++) {
            const int idx = threadIdx.x + it * 128;
            const int row = idx >> 4;
            const int c4  = (idx & 15) << 2;
            const float* src = qkv + (size_t)(b * SEQ + s0 + row) * QKVC + h * 64 + c4;
            *reinterpret_cast<float4*>(&Ks[row][c4]) =
                *reinterpret_cast<const float4*>(src + 768);
            *reinterpret_cast<float4*>(&Vs[row][c4]) =
                *reinterpret_cast<const float4*>(src + 1536);
        }
        __syncthreads();

        float acc_s[8][4];
        #pragma unroll
        for (int j = 0; j < 8; j++)
            #pragma unroll
            for (int q = 0; q < 4; q++) acc_s[j][q] = 0.f;

        #pragma unroll
        for (int ks = 0; ks < 8; ks++) {
            #pragma unroll
            for (int j = 0; j < 8; j++) {
                uint32_t bf[2];
                bf[0] = __float_as_uint(Ks[8 * j + r][8 * ks + c    ]);
                bf[1] = __float_as_uint(Ks[8 * j + r][8 * ks + c + 4]);
                mma_tf32(acc_s[j], aq[ks], bf);
            }
        }

        if (s0 == t0) {
            #pragma unroll
            for (int j = 0; j < 8; j++) {
                const int n = 8 * j + 2 * c;
                const int mr0 = wm + r, mr1 = wm + r + 8;
                if (n     > mr0) acc_s[j][0] = -1e30f;
                if (n + 1 > mr0) acc_s[j][1] = -1e30f;
                if (n     > mr1) acc_s[j][2] = -1e30f;
                if (n + 1 > mr1) acc_s[j][3] = -1e30f;
            }
        }

        float tm0 = -1e30f, tm1 = -1e30f;
        #pragma unroll
        for (int j = 0; j < 8; j++) {
            tm0 = fmaxf(tm0, fmaxf(acc_s[j][0], acc_s[j][1]));
            tm1 = fmaxf(tm1, fmaxf(acc_s[j][2], acc_s[j][3]));
        }
        #pragma unroll
        for (int o = 1; o < 4; o <<= 1) {
            tm0 = fmaxf(tm0, __shfl_xor_sync(0xffffffffu, tm0, o));
            tm1 = fmaxf(tm1, __shfl_xor_sync(0xffffffffu, tm1, o));
        }
        const float mn0 = fmaxf(m0s, tm0);
        const float mn1 = fmaxf(m1s, tm1);
        const float cr0 = __expf(m0s - mn0);
        const float cr1 = __expf(m1s - mn1);

        __syncthreads();

        float sum0 = 0.f, sum1 = 0.f;
        #pragma unroll
        for (int j = 0; j < 8; j++) {
            const float p0 = __expf(acc_s[j][0] - mn0);
            const float p1 = __expf(acc_s[j][1] - mn0);
            const float p2 = __expf(acc_s[j][2] - mn1);
            const float p3 = __expf(acc_s[j][3] - mn1);
            sum0 += p0 + p1;
            sum1 += p2 + p3;
            *reinterpret_cast<float2*>(&Ks[wm + r    ][8 * j + 2 * c]) =
                make_float2(to_tf32(p0), to_tf32(p1));
            *reinterpret_cast<float2*>(&Ks[wm + r + 8][8 * j + 2 * c]) =
                make_float2(to_tf32(p2), to_tf32(p3));
        }
        #pragma unroll
        for (int o = 1; o < 4; o <<= 1) {
            sum0 += __shfl_xor_sync(0xffffffffu, sum0, o);
            sum1 += __shfl_xor_sync(0xffffffffu, sum1, o);
        }
        l0s = l0s * cr0 + sum0;
        l1s = l1s * cr1 + sum1;
        m0s = mn0;
        m1s = mn1;
        #pragma unroll
        for (int j = 0; j < 8; j++) {
            acc_o[j][0] *= cr0; acc_o[j][1] *= cr0;
            acc_o[j][2] *= cr1; acc_o[j][3] *= cr1;
        }
        __syncwarp();

        #pragma unroll
        for (int ks = 0; ks < 8; ks++) {
            uint32_t ap[4];
            ap[0] = __float_as_uint(Ks[wm + r    ][8 * ks + c    ]);
            ap[1] = __float_as_uint(Ks[wm + r + 8][8 * ks + c    ]);
            ap[2] = __float_as_uint(Ks[wm + r    ][8 * ks + c + 4]);
            ap[3] = __float_as_uint(Ks[wm + r + 8][8 * ks + c + 4]);
            #pragma unroll
            for (int j = 0; j < 8; j++) {
                uint32_t bf[2];
                bf[0] = __float_as_uint(Vs[8 * ks + c    ][8 * j + r]);
                bf[1] = __float_as_uint(Vs[8 * ks + c + 4][8 * j + r]);
                mma_tf32(acc_o[j], ap, bf);
            }
        }
    }

    const float inv0 = 1.f / l0s;
    const float inv1 = 1.f / l1s;
    float* y0 = Y + (size_t)(b * SEQ + t0 + wm + r) * DIM + h * 64;
    float* y1 = y0 + 8 * (size_t)DIM;
    #pragma unroll
    for (int j = 0; j < 8; j++) {
        const int n = 8 * j + 2 * c;         // even
        const int p = PERMC(n);              // n+1 -> p+4
        y0[p]     = to_tf32(acc_o[j][0] * inv0);
        y0[p + 4] = to_tf32(acc_o[j][1] * inv0);
        y1[p]     = to_tf32(acc_o[j][2] * inv1);
        y1[p + 4] = to_tf32(acc_o[j][3] * inv1);
    }
}

// ---------------- launch ----------------
extern "C" void kernel_launch(void* const* d_in, const int* in_sizes, int n_in,
                              void* d_out, int out_size) {
    const float* X   = (const float*)d_in[0];
    const float* w_q = (const float*)d_in[1];
    const float* w_k = (const float*)d_in[2];
    const float* w_v = (const float*)d_in[3];
    const float* w_o = (const float*)d_in[4];
    const float* W1  = (const float*)d_in[5];
    const float* b1  = (const float*)d_in[6];
    const float* W2  = (const float*)d_in[7];
    const float* b2  = (const float*)d_in[8];
    const float* g1  = (const float*)d_in[9];
    const float* be1 = (const float*)d_in[10];
    const float* g2  = (const float*)d_in[11];
    const float* be2 = (const float*)d_in[12];
    float* out = (float*)d_out;

    float *p_ln1, *p_qkv, *p_y, *p_x2, *p_ln2, *p_h;
    float *p_wqkv, *p_woT, *p_w1, *p_w2;
    cudaGetSymbolAddress((void**)&p_ln1,  g_ln1);
    cudaGetSymbolAddress((void**)&p_qkv,  g_qkv);
    cudaGetSymbolAddress((void**)&p_y,    g_y);
    cudaGetSymbolAddress((void**)&p_x2,   g_x2);
    cudaGetSymbolAddress((void**)&p_ln2,  g_ln2);
    cudaGetSymbolAddress((void**)&p_h,    g_h);
    cudaGetSymbolAddress((void**)&p_wqkv, g_wqkv);
    cudaGetSymbolAddress((void**)&p_woT,  g_woT);
    cudaGetSymbolAddress((void**)&p_w1,   g_w1);
    cudaGetSymbolAddress((void**)&p_w2,   g_w2);

    // launch 0: prep QKV weights (k-permuted)
    prep_qkv_kernel<<<(3 * NW + 255) / 256, 256>>>(w_q, w_k, w_v, p_wqkv);
    // launch 1: prep MLP weights + w_o transpose (k-permuted)
    {
        const int tot = 2 * DFF * DIM + NW;
        prep_mlp_kernel<<<(tot + 255) / 256, 256>>>(W1, W2, w_o, p_w1, p_w2, p_woT);
    }
    // launch 2: LN1 (perm out)
    ln_kernel<<<ROWS, 256>>>(X, g1, be1, p_ln1);
    // launch 3: fused QKV projection (natural tf32 out for attention)
    {
        dim3 grid(QKVC / 128, ROWS / 128);
        gemm_tc<false,false,false,true,false><<<grid, 128>>>(p_ln1, p_wqkv, nullptr, nullptr, p_qkv, ROWS, QKVC, DIM);
    }
    // launch 4: flash attention (perm tf32 Y)
    {
        dim3 grid(SEQ / 64, HEADS, BATCH);
        flash_attn<<<grid, 128>>>(p_qkv, p_y);
    }
    // launch 5 (ncu -s 5): O-projection + residual (natural out -> ln2)
    {
        dim3 grid(DIM / 128, ROWS / 128);
        gemm_tc<false,false,true,false,false><<<grid, 128>>>(p_y, p_woT, nullptr, X, p_x2, ROWS, DIM, DIM);
    }
    // launch 6: LN2 (perm out)
    ln_kernel<<<ROWS, 256>>>(p_x2, g2, be2, p_ln2);
    // launch 7: MLP up (perm tf32 out -> MLP down A)
    {
        dim3 grid(DFF / 128, ROWS / 128);
        gemm_tc<true,true,false,true,true><<<grid, 128>>>(p_ln2, p_w1, b1, nullptr, p_h, ROWS, DFF, DIM);
    }
    // launch 8: MLP down + bias + residual -> out (natural)
    {
        dim3 grid(DIM / 128, ROWS / 128);
        gemm_tc<true,false,true,false,false><<<grid, 128>>>(p_h, p_w2, b2, p_x2, out, ROWS, DIM, DFF);
    }
}